// round 8
// baseline (speedup 1.0000x reference)
#include <cuda_runtime.h>
#include <cstdint>

#define B 256
#define L 128
#define F 256
#define S 512
#define BF (B*F)
#define G4F 1024

// ---- static device scratch (no allocation) ----
__device__ float g_Wc[G4F * F];     // combined W_ih+W_hh, permuted [nf*128+c][k], tf32-rounded
__device__ float g_WihT[G4F * F];   // [(nf*256+k)*128 + c]  (permuted c)
__device__ float g_WhhT[G4F * F];
__device__ float g_WiT[L * F];      // [k*256 + f]
__device__ float g_bc[G4F];         // permuted combined bias
__device__ float g_init[B * F];
__device__ float g_c1[B * F];

__device__ __forceinline__ float sigf(float x) { return 1.0f / (1.0f + expf(-x)); }
__device__ __forceinline__ float tanhfast(float x) {
    float r; asm("tanh.approx.f32 %0, %1;" : "=f"(r) : "f"(x)); return r;
}
__device__ __forceinline__ float sigfast(float x) { return 0.5f * tanhfast(0.5f * x) + 0.5f; }
__device__ __forceinline__ unsigned tf32r(float x) {
    unsigned u; asm("cvt.rna.tf32.f32 %0, %1;" : "=r"(u) : "f"(x)); return u;
}

// ---- mbarrier / bulk-copy helpers ----
__device__ __forceinline__ void mbar_init(uint32_t mbar, uint32_t cnt) {
    asm volatile("mbarrier.init.shared.b64 [%0], %1;" :: "r"(mbar), "r"(cnt) : "memory");
}
__device__ __forceinline__ void mbar_expect_tx(uint32_t mbar, uint32_t bytes) {
    asm volatile("mbarrier.arrive.expect_tx.shared.b64 _, [%0], %1;"
                 :: "r"(mbar), "r"(bytes) : "memory");
}
__device__ __forceinline__ void mbar_wait(uint32_t mbar, uint32_t parity) {
    asm volatile(
        "{\n\t.reg .pred P;\n"
        "WL%=:\n\t"
        "mbarrier.try_wait.parity.acquire.cta.shared::cta.b64 P, [%0], %1, 0x989680;\n\t"
        "@P bra WD%=;\n\t"
        "bra WL%=;\n"
        "WD%=:\n\t}"
        :: "r"(mbar), "r"(parity) : "memory");
}
// 128B global->shared bulk copy, multicast to all CTAs in cluster mask,
// complete_tx on each receiver's local mbarrier (same smem offset).
__device__ __forceinline__ void bulk_mc(uint32_t dst, const float* src, uint32_t bytes,
                                        uint32_t mbar, uint16_t mask) {
    asm volatile(
        "cp.async.bulk.shared::cluster.global.mbarrier::complete_tx::bytes.multicast::cluster "
        "[%0], [%1], %2, [%3], %4;"
        :: "r"(dst), "l"(src), "r"(bytes), "r"(mbar), "h"(mask) : "memory");
}

// ---- P0: weight prep ----
__global__ void prep_kernel(const float* __restrict__ Wih, const float* __restrict__ Whh,
                            const float* __restrict__ bih, const float* __restrict__ bhh,
                            const float* __restrict__ Wi) {
    int bid = blockIdx.x, tid = threadIdx.x;
    if (bid < 1024) {
        int r = bid, k = tid;
        int g = r >> 8;
        int jj = r & 255;
        int nf = jj >> 5;
        int j  = jj & 31;
        int c  = ((j >> 3) << 5) + (g << 3) + (j & 7);
        float wih = Wih[r * 256 + k];
        float whh = Whh[r * 256 + k];
        g_Wc[(nf * 128 + c) * 256 + k] = __uint_as_float(tf32r(wih + whh));
        g_WihT[(nf * 256 + k) * 128 + c] = wih;
        g_WhhT[(nf * 256 + k) * 128 + c] = whh;
        if (k == 0) g_bc[nf * 128 + c] = bih[r] + bhh[r];
    } else {
        int k = bid - 1024;
        int f = tid;
        g_WiT[k * 256 + f] = Wi[f * 128 + k];
    }
}

// ---- P1: init = elu(x @ Wi.T + bi) ----
__global__ void init_kernel(const float* __restrict__ x, const float* __restrict__ bi) {
    __shared__ float xs[32 * 128];
    int bid = blockIdx.x, tid = threadIdx.x;
    int bt = bid >> 2, ft = bid & 3;
    for (int i = tid; i < 32 * 128; i += 256)
        xs[i] = x[(bt * 32 + (i >> 7)) * 128 + (i & 127)];
    __syncthreads();
    int tx = tid & 15, ty = tid >> 4;
    int b0 = ty * 2;
    int f0 = ft * 64 + tx * 4;
    float acc[2][4] = {};
#pragma unroll 4
    for (int k = 0; k < 128; ++k) {
        float4 w = *(const float4*)&g_WiT[k * 256 + f0];
        float x0 = xs[b0 * 128 + k];
        float x1 = xs[(b0 + 1) * 128 + k];
        acc[0][0] += x0 * w.x; acc[0][1] += x0 * w.y; acc[0][2] += x0 * w.z; acc[0][3] += x0 * w.w;
        acc[1][0] += x1 * w.x; acc[1][1] += x1 * w.y; acc[1][2] += x1 * w.z; acc[1][3] += x1 * w.w;
    }
#pragma unroll
    for (int r = 0; r < 2; ++r)
#pragma unroll
        for (int cc = 0; cc < 4; ++cc) {
            float v = acc[r][cc] + bi[f0 + cc];
            v = (v > 0.0f) ? v : expm1f(v);
            g_init[(bt * 32 + b0 + r) * 256 + f0 + cc] = v;
        }
}

// ---- P2: step 0 (inp = last_feat, h = c = init) ----
__global__ void step0_kernel(const float* __restrict__ lf, float* __restrict__ d_out) {
    extern __shared__ float sm[];
    float* lfs = sm;
    float* ins = lfs + 16 * 256;
    float* wih = ins + 16 * 256;
    float* whh = wih + 64 * 128;
    int tid = threadIdx.x;
    int nf = blockIdx.x & 7, mbt = blockIdx.x >> 3;
    for (int i = tid; i < 16 * 256; i += 256) {
        int gi = (mbt * 16 + (i >> 8)) * 256 + (i & 255);
        lfs[i] = lf[gi];
        ins[i] = g_init[gi];
    }
    int tx = tid & 31, ty = tid >> 5;
    int c0 = tx * 4;
    float acc[2][4] = {};
    for (int kc = 0; kc < 4; ++kc) {
        __syncthreads();
        for (int i = tid; i < 64 * 128; i += 256) {
            int k = kc * 64 + (i >> 7), c = i & 127;
            wih[i] = g_WihT[(nf * 256 + k) * 128 + c];
            whh[i] = g_WhhT[(nf * 256 + k) * 128 + c];
        }
        __syncthreads();
#pragma unroll 4
        for (int k = 0; k < 64; ++k) {
            float4 a4 = *(const float4*)&wih[k * 128 + c0];
            float4 b4 = *(const float4*)&whh[k * 128 + c0];
#pragma unroll
            for (int e = 0; e < 2; ++e) {
                int b = ty + 8 * e;
                float lv = lfs[b * 256 + kc * 64 + k];
                float iv = ins[b * 256 + kc * 64 + k];
                acc[e][0] += lv * a4.x + iv * b4.x;
                acc[e][1] += lv * a4.y + iv * b4.y;
                acc[e][2] += lv * a4.z + iv * b4.z;
                acc[e][3] += lv * a4.w + iv * b4.w;
            }
        }
    }
    __syncthreads();
    float* gss = lfs;
#pragma unroll
    for (int e = 0; e < 2; ++e)
#pragma unroll
        for (int cc = 0; cc < 4; ++cc)
            gss[(ty + 8 * e) * 132 + c0 + cc] = acc[e][cc];
    __syncthreads();
#pragma unroll
    for (int e2 = 0; e2 < 2; ++e2) {
        int li = tid + 256 * e2;
        int b = li >> 5, j = li & 31;
        int cb = ((j >> 3) << 5) + (j & 7);
        float iv = gss[b * 132 + cb]      + g_bc[nf * 128 + cb];
        float fv = gss[b * 132 + cb + 8]  + g_bc[nf * 128 + cb + 8];
        float gv = gss[b * 132 + cb + 16] + g_bc[nf * 128 + cb + 16];
        float ov = gss[b * 132 + cb + 24] + g_bc[nf * 128 + cb + 24];
        float cp = ins[b * 256 + nf * 32 + j];
        float cn = sigf(fv) * cp + sigf(iv) * tanhf(gv);
        float hn = sigf(ov) * tanhf(cn);
        int gi = (mbt * 16 + b) * 256 + nf * 32 + j;
        g_c1[gi] = cn;
        d_out[gi] = hn;
    }
}

// ---- tf32 mma helper ----
__device__ __forceinline__ void mma8(float* d, const unsigned* a, unsigned b0, unsigned b1) {
    asm volatile(
        "mma.sync.aligned.m16n8k8.row.col.f32.tf32.tf32.f32 "
        "{%0,%1,%2,%3}, {%4,%5,%6,%7}, {%8,%9}, {%0,%1,%2,%3};"
        : "+f"(d[0]), "+f"(d[1]), "+f"(d[2]), "+f"(d[3])
        : "r"(a[0]), "r"(a[1]), "r"(a[2]), "r"(a[3]), "r"(b0), "r"(b1));
}

// ---- P3: persistent recurrence, t = 1..511 ----
// 128 CTAs x 256 thr, clusters of 8 (= batch group mb). nf = rank = bid&7.
// h exchange: each CTA bulk-copy-multicasts its d_out slice (16 rows x 128B) into all
// 8 peers' hs buffer; consumers wait one local transaction mbarrier (expect_tx 16KB).
__global__ void __cluster_dims__(8, 1, 1) __launch_bounds__(256, 1)
lstm_kernel(float* __restrict__ d_out) {
    __shared__ __align__(16) float hs[2][16 * 260];   // double-buffered h (raw fp32)
    __shared__ float red[128 * 20];                   // k-split partials
    __shared__ __align__(8) unsigned long long mbars[2];  // full[0], full[1]

    int tid = threadIdx.x;
    int nf = blockIdx.x & 7, mb = blockIdx.x >> 3;
    int warp = tid >> 5, lane = tid & 31;
    int cg = warp & 3, ks = warp >> 2;
    int gID = lane >> 2, tig = lane & 3;

    uint32_t hs_base = (uint32_t)__cvta_generic_to_shared(&hs[0][0]);
    uint32_t mb_base = (uint32_t)__cvta_generic_to_shared(&mbars[0]);

    if (tid == 0) { mbar_init(mb_base, 1); mbar_init(mb_base + 8, 1); }

    // B fragments in registers: warp covers cols [cg*32,+32), k in [ks*128,+128)
    unsigned breg[4][16][2];
#pragma unroll
    for (int nt = 0; nt < 4; ++nt)
#pragma unroll
        for (int kb = 0; kb < 16; ++kb) {
            const float* wp = &g_Wc[(nf * 128 + cg * 32 + nt * 8 + gID) * 256 + ks * 128 + kb * 8 + tig];
            breg[nt][kb][0] = __float_as_uint(wp[0]);
            breg[nt][kb][1] = __float_as_uint(wp[4]);
        }

    float bias[4][2];
#pragma unroll
    for (int nt = 0; nt < 4; ++nt) {
        float b0 = g_bc[nf * 128 + cg * 32 + nt * 8 + 2 * tig];
        float b1 = g_bc[nf * 128 + cg * 32 + nt * 8 + 2 * tig + 1];
        bias[nt][0] = ks ? 0.0f : b0;
        bias[nt][1] = ks ? 0.0f : b1;
    }

    float creg[4];
    if (ks == 0) {
#pragma unroll
        for (int rh = 0; rh < 2; ++rh)
#pragma unroll
            for (int ff = 0; ff < 2; ++ff)
                creg[rh * 2 + ff] =
                    g_c1[(mb * 16 + gID + rh * 8) * 256 + nf * 32 + cg * 8 + 2 * tig + ff];
    }
    __syncthreads();
    // cluster-wide: all mbarriers initialized before any multicast copy targets them
    asm volatile("barrier.cluster.arrive.aligned;" ::: "memory");
    asm volatile("barrier.cluster.wait.aligned;" ::: "memory");

    // prologue: multicast own slice of h_1 (d_out row 0, by step0) into hs[1] everywhere
    if (tid == 0) {
        mbar_expect_tx(mb_base + 8, 16384);
        const float* src = d_out + (size_t)mb * 4096 + nf * 32;
        uint32_t dst = hs_base + 16640 + nf * 128;     // hs[1] + col nf*32
#pragma unroll
        for (int r = 0; r < 16; ++r)
            bulk_mc(dst + r * 1040, src + r * 256, 128, mb_base + 8, 0xFFu);
    }

    unsigned ph[2] = {0u, 0u};

    for (int t = 1; t < 512; ++t) {
        int b = t & 1;
        mbar_wait(mb_base + 8 * b, ph[b]);
        ph[b] ^= 1u;

        // gates(16x32 this cg) = hs[b](k-half) @ Wc^T  (A = raw fp32, HW-truncated to tf32)
        float acc[4][4];
#pragma unroll
        for (int nt = 0; nt < 4; ++nt) {
            acc[nt][0] = bias[nt][0]; acc[nt][1] = bias[nt][1];
            acc[nt][2] = bias[nt][0]; acc[nt][3] = bias[nt][1];
        }
        const float* hb = &hs[b][0];
#pragma unroll
        for (int kb = 0; kb < 16; ++kb) {
            int k0 = ks * 128 + kb * 8;
            unsigned a[4];
            a[0] = __float_as_uint(hb[gID * 260 + k0 + tig]);
            a[1] = __float_as_uint(hb[(gID + 8) * 260 + k0 + tig]);
            a[2] = __float_as_uint(hb[gID * 260 + k0 + 4 + tig]);
            a[3] = __float_as_uint(hb[(gID + 8) * 260 + k0 + 4 + tig]);
#pragma unroll
            for (int nt = 0; nt < 4; ++nt)
                mma8(acc[nt], a, breg[nt][kb][0], breg[nt][kb][1]);
        }
        if (ks == 1) {
            float* rp = &red[(cg * 32 + lane) * 20];
#pragma unroll
            for (int nt = 0; nt < 4; ++nt)
                *(float4*)(rp + nt * 4) = make_float4(acc[nt][0], acc[nt][1], acc[nt][2], acc[nt][3]);
        }
        __syncthreads();   // all hs[b] reads done; red visible

        if (ks == 0) {
            const float* rp = &red[(cg * 32 + lane) * 20];
#pragma unroll
            for (int nt = 0; nt < 4; ++nt) {
                float4 r4 = *(const float4*)(rp + nt * 4);
                acc[nt][0] += r4.x; acc[nt][1] += r4.y;
                acc[nt][2] += r4.z; acc[nt][3] += r4.w;
            }
            float hn[2][2];
#pragma unroll
            for (int rh = 0; rh < 2; ++rh)
#pragma unroll
                for (int ff = 0; ff < 2; ++ff) {
                    int q = rh * 2 + ff;
                    float cn = sigfast(acc[1][q]) * creg[q] + sigfast(acc[0][q]) * tanhfast(acc[2][q]);
                    hn[rh][ff] = sigfast(acc[3][q]) * tanhfast(cn);
                    creg[q] = cn;
                }
            // h -> d_out (output AND the source for the multicast exchange)
            float* dst = d_out + (size_t)t * BF + (size_t)mb * 4096;
#pragma unroll
            for (int rh = 0; rh < 2; ++rh)
                *(float2*)(dst + (gID + rh * 8) * 256 + nf * 32 + cg * 8 + 2 * tig) =
                    make_float2(hn[rh][0], hn[rh][1]);

            asm volatile("bar.sync 1, 128;" ::: "memory");   // slice fully stored
            if (tid == 0 && t < 511) {
                asm volatile("membar.gl;" ::: "memory");
                asm volatile("fence.proxy.async;" ::: "memory");
                int b2 = b ^ 1;
                uint32_t fb2 = mb_base + 8 * b2;
                mbar_expect_tx(fb2, 16384);                  // also releases ks=1 warps
                const float* src = dst + nf * 32;
                uint32_t dsts = hs_base + (uint32_t)b2 * 16640 + nf * 128;
#pragma unroll
                for (int r = 0; r < 16; ++r)
                    bulk_mc(dsts + r * 1040, src + r * 256, 128, fb2, 0xFFu);
            }
        }
        // no bottom sync: next wait on full[b^1] can only pass after local expect_tx
        // (arrive count 1) + all 8 slices (16KB) delivered.
    }

    asm volatile("barrier.cluster.arrive.aligned;" ::: "memory");
    asm volatile("barrier.cluster.wait.aligned;" ::: "memory");
}

extern "C" void kernel_launch(void* const* d_in, const int* in_sizes, int n_in,
                              void* d_out, int out_size) {
    const float* x   = (const float*)d_in[0];
    const float* lf  = (const float*)d_in[1];
    const float* Wi  = (const float*)d_in[2];
    const float* bi  = (const float*)d_in[3];
    const float* Wih = (const float*)d_in[4];
    const float* Whh = (const float*)d_in[5];
    const float* bih = (const float*)d_in[6];
    const float* bhh = (const float*)d_in[7];
    float* out = (float*)d_out;

    cudaFuncSetAttribute(step0_kernel, cudaFuncAttributeMaxDynamicSharedMemorySize, 98304);

    prep_kernel<<<1152, 256>>>(Wih, Whh, bih, bhh, Wi);
    init_kernel<<<32, 256>>>(x, bi);
    step0_kernel<<<128, 256, 98304>>>(lf, out);
    lstm_kernel<<<128, 256>>>(out);
}

// round 10
// speedup vs baseline: 1.1518x; 1.1518x over previous
#include <cuda_runtime.h>
#include <cuda_fp16.h>
#include <cstdint>

#define B 256
#define L 128
#define F 256
#define S 512
#define BF (B*F)
#define G4F 1024

// ---- static device scratch (no allocation) ----
__device__ __half g_Wch[G4F * F];   // combined W_ih+W_hh, permuted [nf*128+c][k], fp16
__device__ float  g_WihT[G4F * F];  // [(nf*256+k)*128 + c]  (permuted c)
__device__ float  g_WhhT[G4F * F];
__device__ float  g_WiT[L * F];     // [k*256 + f]
__device__ float  g_bc[G4F];        // permuted combined bias
__device__ float  g_init[B * F];
__device__ float  g_c1[B * F];

__device__ __forceinline__ float sigf(float x) { return 1.0f / (1.0f + expf(-x)); }
__device__ __forceinline__ float tanhfast(float x) {
    float r; asm("tanh.approx.f32 %0, %1;" : "=f"(r) : "f"(x)); return r;
}
__device__ __forceinline__ float sigfast(float x) { return 0.5f * tanhfast(0.5f * x) + 0.5f; }

// ---- cluster / mbarrier helpers ----
__device__ __forceinline__ void mbar_init(uint32_t mbar, uint32_t cnt) {
    asm volatile("mbarrier.init.shared.b64 [%0], %1;" :: "r"(mbar), "r"(cnt) : "memory");
}
__device__ __forceinline__ void mbar_wait_cl(uint32_t mbar, uint32_t parity) {
    asm volatile(
        "{\n\t.reg .pred P;\n"
        "WL%=:\n\t"
        "mbarrier.try_wait.parity.acquire.cluster.shared::cta.b64 P, [%0], %1, 0x989680;\n\t"
        "@P bra WD%=;\n\t"
        "bra WL%=;\n"
        "WD%=:\n\t}"
        :: "r"(mbar), "r"(parity) : "memory");
}
__device__ __forceinline__ void mbar_arrive_rel(uint32_t remote_addr) {
    asm volatile("mbarrier.arrive.release.cluster.shared::cluster.b64 _, [%0];"
                 :: "r"(remote_addr) : "memory");
}
__device__ __forceinline__ uint32_t mapa_u32(uint32_t local, uint32_t rank) {
    uint32_t r;
    asm("mapa.shared::cluster.u32 %0, %1, %2;" : "=r"(r) : "r"(local), "r"(rank));
    return r;
}
__device__ __forceinline__ void st_cluster_u32(uint32_t addr, uint32_t v) {
    asm volatile("st.shared::cluster.u32 [%0], %1;" :: "r"(addr), "r"(v) : "memory");
}
__device__ __forceinline__ uint32_t pack_h2(float a, float b) {
    __half2 h = __floats2half2_rn(a, b);
    return *(uint32_t*)&h;
}

// ---- P0: weight prep ----
// col permutation within a 128-col slice: c = (j>>3)*32 + gate*8 + (j&7)
__global__ void prep_kernel(const float* __restrict__ Wih, const float* __restrict__ Whh,
                            const float* __restrict__ bih, const float* __restrict__ bhh,
                            const float* __restrict__ Wi) {
    int bid = blockIdx.x, tid = threadIdx.x;
    if (bid < 1024) {
        int r = bid, k = tid;
        int g = r >> 8;
        int jj = r & 255;
        int nf = jj >> 5;
        int j  = jj & 31;
        int c  = ((j >> 3) << 5) + (g << 3) + (j & 7);
        float wih = Wih[r * 256 + k];
        float whh = Whh[r * 256 + k];
        g_Wch[(nf * 128 + c) * 256 + k] = __float2half_rn(wih + whh);
        g_WihT[(nf * 256 + k) * 128 + c] = wih;
        g_WhhT[(nf * 256 + k) * 128 + c] = whh;
        if (k == 0) g_bc[nf * 128 + c] = bih[r] + bhh[r];
    } else {
        int k = bid - 1024;
        int f = tid;
        g_WiT[k * 256 + f] = Wi[f * 128 + k];
    }
}

// ---- P1: init = elu(x @ Wi.T + bi) ----
__global__ void init_kernel(const float* __restrict__ x, const float* __restrict__ bi) {
    __shared__ float xs[32 * 128];
    int bid = blockIdx.x, tid = threadIdx.x;
    int bt = bid >> 2, ft = bid & 3;
    for (int i = tid; i < 32 * 128; i += 256)
        xs[i] = x[(bt * 32 + (i >> 7)) * 128 + (i & 127)];
    __syncthreads();
    int tx = tid & 15, ty = tid >> 4;
    int b0 = ty * 2;
    int f0 = ft * 64 + tx * 4;
    float acc[2][4] = {};
#pragma unroll 4
    for (int k = 0; k < 128; ++k) {
        float4 w = *(const float4*)&g_WiT[k * 256 + f0];
        float x0 = xs[b0 * 128 + k];
        float x1 = xs[(b0 + 1) * 128 + k];
        acc[0][0] += x0 * w.x; acc[0][1] += x0 * w.y; acc[0][2] += x0 * w.z; acc[0][3] += x0 * w.w;
        acc[1][0] += x1 * w.x; acc[1][1] += x1 * w.y; acc[1][2] += x1 * w.z; acc[1][3] += x1 * w.w;
    }
#pragma unroll
    for (int r = 0; r < 2; ++r)
#pragma unroll
        for (int cc = 0; cc < 4; ++cc) {
            float v = acc[r][cc] + bi[f0 + cc];
            v = (v > 0.0f) ? v : expm1f(v);
            g_init[(bt * 32 + b0 + r) * 256 + f0 + cc] = v;
        }
}

// ---- P2: step 0 (inp = last_feat, h = c = init) ----
__global__ void step0_kernel(const float* __restrict__ lf, float* __restrict__ d_out) {
    extern __shared__ float sm[];
    float* lfs = sm;
    float* ins = lfs + 16 * 256;
    float* wih = ins + 16 * 256;
    float* whh = wih + 64 * 128;
    int tid = threadIdx.x;
    int nf = blockIdx.x & 7, mbt = blockIdx.x >> 3;
    for (int i = tid; i < 16 * 256; i += 256) {
        int gi = (mbt * 16 + (i >> 8)) * 256 + (i & 255);
        lfs[i] = lf[gi];
        ins[i] = g_init[gi];
    }
    int tx = tid & 31, ty = tid >> 5;
    int c0 = tx * 4;
    float acc[2][4] = {};
    for (int kc = 0; kc < 4; ++kc) {
        __syncthreads();
        for (int i = tid; i < 64 * 128; i += 256) {
            int k = kc * 64 + (i >> 7), c = i & 127;
            wih[i] = g_WihT[(nf * 256 + k) * 128 + c];
            whh[i] = g_WhhT[(nf * 256 + k) * 128 + c];
        }
        __syncthreads();
#pragma unroll 4
        for (int k = 0; k < 64; ++k) {
            float4 a4 = *(const float4*)&wih[k * 128 + c0];
            float4 b4 = *(const float4*)&whh[k * 128 + c0];
#pragma unroll
            for (int e = 0; e < 2; ++e) {
                int b = ty + 8 * e;
                float lv = lfs[b * 256 + kc * 64 + k];
                float iv = ins[b * 256 + kc * 64 + k];
                acc[e][0] += lv * a4.x + iv * b4.x;
                acc[e][1] += lv * a4.y + iv * b4.y;
                acc[e][2] += lv * a4.z + iv * b4.z;
                acc[e][3] += lv * a4.w + iv * b4.w;
            }
        }
    }
    __syncthreads();
    float* gss = lfs;
#pragma unroll
    for (int e = 0; e < 2; ++e)
#pragma unroll
        for (int cc = 0; cc < 4; ++cc)
            gss[(ty + 8 * e) * 132 + c0 + cc] = acc[e][cc];
    __syncthreads();
#pragma unroll
    for (int e2 = 0; e2 < 2; ++e2) {
        int li = tid + 256 * e2;
        int b = li >> 5, j = li & 31;
        int cb = ((j >> 3) << 5) + (j & 7);
        float iv = gss[b * 132 + cb]      + g_bc[nf * 128 + cb];
        float fv = gss[b * 132 + cb + 8]  + g_bc[nf * 128 + cb + 8];
        float gv = gss[b * 132 + cb + 16] + g_bc[nf * 128 + cb + 16];
        float ov = gss[b * 132 + cb + 24] + g_bc[nf * 128 + cb + 24];
        float cp = ins[b * 256 + nf * 32 + j];
        float cn = sigf(fv) * cp + sigf(iv) * tanhf(gv);
        float hn = sigf(ov) * tanhf(cn);
        int gi = (mbt * 16 + b) * 256 + nf * 32 + j;
        g_c1[gi] = cn;
        d_out[gi] = hn;
    }
}

// ---- fp16 mma helper (m16n8k16, fp32 accum) ----
__device__ __forceinline__ void mma16(float* d, const unsigned* a, unsigned b0, unsigned b1) {
    asm volatile(
        "mma.sync.aligned.m16n8k16.row.col.f32.f16.f16.f32 "
        "{%0,%1,%2,%3}, {%4,%5,%6,%7}, {%8,%9}, {%0,%1,%2,%3};"
        : "+f"(d[0]), "+f"(d[1]), "+f"(d[2]), "+f"(d[3])
        : "r"(a[0]), "r"(a[1]), "r"(a[2]), "r"(a[3]), "r"(b0), "r"(b1));
}

#define HSTRIDE 264              // halves per row (528 B) -> conflict-free fragments
#define HBUFB   (16 * HSTRIDE * 2)  // bytes per h buffer (8448)

// ---- P3: persistent recurrence, t = 1..511 ----
// 128 CTAs x 256 thr, clusters of 8 (= batch group mb). nf = bid&7.
// h lives ONLY in SMEM (fp16): each CTA pushes its 16x32 slice into all 8 peers'
// hs buffer via st.shared::cluster, signaled by per-slice mbarriers (count 128).
// Consumers wait slice j just before its k-chunk mma -> exchange overlaps compute.
__global__ void __cluster_dims__(8, 1, 1) __launch_bounds__(256, 1)
lstm_kernel(float* __restrict__ d_out) {
    __shared__ __align__(16) __half hs[2][16 * HSTRIDE];
    __shared__ float red[128 * 20];
    __shared__ __align__(8) unsigned long long mbars[16];   // [buf][slice]

    int tid = threadIdx.x;
    int nf = blockIdx.x & 7, mb = blockIdx.x >> 3;
    int warp = tid >> 5, lane = tid & 31;
    int cg = warp & 3, ks = warp >> 2;
    int gID = lane >> 2, tig = lane & 3;

    uint32_t hsb = (uint32_t)__cvta_generic_to_shared(&hs[0][0]);
    uint32_t mbb = (uint32_t)__cvta_generic_to_shared(&mbars[0]);

    if (tid == 0) {
#pragma unroll
        for (int i = 0; i < 16; ++i) mbar_init(mbb + i * 8, 128);
    }

    // weight fragments (fp16): warp covers cols [cg*32,+32), k in [ks*128,+128)
    unsigned breg[4][8][2];
#pragma unroll
    for (int nt = 0; nt < 4; ++nt)
#pragma unroll
        for (int kb = 0; kb < 8; ++kb) {
            const __half* wp = &g_Wch[(nf * 128 + cg * 32 + nt * 8 + gID) * 256
                                      + ks * 128 + kb * 16 + 2 * tig];
            breg[nt][kb][0] = *(const uint32_t*)wp;        // k = k0+2tig, +1
            breg[nt][kb][1] = *(const uint32_t*)(wp + 8);  // k = k0+2tig+8, +9
        }

    float bias[4][2];
#pragma unroll
    for (int nt = 0; nt < 4; ++nt) {
        float b0 = g_bc[nf * 128 + cg * 32 + nt * 8 + 2 * tig];
        float b1 = g_bc[nf * 128 + cg * 32 + nt * 8 + 2 * tig + 1];
        bias[nt][0] = ks ? 0.0f : b0;
        bias[nt][1] = ks ? 0.0f : b1;
    }

    // peer SMEM bases
    uint32_t peer_hs[8], peer_mb[8];
#pragma unroll
    for (int p = 0; p < 8; ++p) {
        peer_hs[p] = mapa_u32(hsb, p);
        peer_mb[p] = mapa_u32(mbb, p);
    }

    float creg[4];
    uint32_t hoff[2];   // byte offsets of this thread's half2 within an h buffer
    if (ks == 0) {
#pragma unroll
        for (int rh = 0; rh < 2; ++rh) {
#pragma unroll
            for (int ff = 0; ff < 2; ++ff)
                creg[rh * 2 + ff] =
                    g_c1[(mb * 16 + gID + rh * 8) * 256 + nf * 32 + cg * 8 + 2 * tig + ff];
            hoff[rh] = (uint32_t)((gID + rh * 8) * HSTRIDE + nf * 32 + cg * 8 + 2 * tig) * 2;
        }
    }
    __syncthreads();
    // cluster-wide: all mbarriers initialized before any remote store/arrive
    asm volatile("barrier.cluster.arrive.aligned;" ::: "memory");
    asm volatile("barrier.cluster.wait.aligned;" ::: "memory");

    // prologue: push own slice of h_1 (d_out row 0, from step0) into buffer 1 everywhere
    if (ks == 0) {
        const float* src = d_out + (size_t)mb * 4096;
#pragma unroll
        for (int rh = 0; rh < 2; ++rh) {
            float2 v = *(const float2*)(src + (gID + rh * 8) * 256 + nf * 32 + cg * 8 + 2 * tig);
            uint32_t hv = pack_h2(v.x, v.y);
#pragma unroll
            for (int p = 0; p < 8; ++p)
                st_cluster_u32(peer_hs[p] + HBUFB + hoff[rh], hv);
        }
#pragma unroll
        for (int p = 0; p < 8; ++p)
            mbar_arrive_rel(peer_mb[p] + (8 + nf) * 8);
    }

    unsigned ph[2] = {0u, 0u};

    for (int t = 1; t < 512; ++t) {
        int b = t & 1;
        const __half* hb = &hs[b][0];

        float acc[4][4];
#pragma unroll
        for (int nt = 0; nt < 4; ++nt) {
            acc[nt][0] = bias[nt][0]; acc[nt][1] = bias[nt][1];
            acc[nt][2] = bias[nt][0]; acc[nt][3] = bias[nt][1];
        }

        // mma, slice by slice; wait each slice barrier just-in-time
#pragma unroll
        for (int sl = 0; sl < 4; ++sl) {
            int j = ks * 4 + sl;
            mbar_wait_cl(mbb + (b * 8 + j) * 8, ph[b]);
#pragma unroll
            for (int kb2 = 0; kb2 < 2; ++kb2) {
                int k0 = j * 32 + kb2 * 16;
                unsigned a[4];
                a[0] = *(const uint32_t*)&hb[gID * HSTRIDE + k0 + 2 * tig];
                a[1] = *(const uint32_t*)&hb[(gID + 8) * HSTRIDE + k0 + 2 * tig];
                a[2] = *(const uint32_t*)&hb[gID * HSTRIDE + k0 + 8 + 2 * tig];
                a[3] = *(const uint32_t*)&hb[(gID + 8) * HSTRIDE + k0 + 8 + 2 * tig];
                int kb = sl * 2 + kb2;
#pragma unroll
                for (int nt = 0; nt < 4; ++nt)
                    mma16(acc[nt], a, breg[nt][kb][0], breg[nt][kb][1]);
            }
        }
        ph[b] ^= 1u;

        if (ks == 1) {
            float* rp = &red[(cg * 32 + lane) * 20];
#pragma unroll
            for (int nt = 0; nt < 4; ++nt)
                *(float4*)(rp + nt * 4) = make_float4(acc[nt][0], acc[nt][1], acc[nt][2], acc[nt][3]);
        }
        __syncthreads();   // red visible; all local hs[b] reads retired

        if (ks == 0) {
            const float* rp = &red[(cg * 32 + lane) * 20];
#pragma unroll
            for (int nt = 0; nt < 4; ++nt) {
                float4 r4 = *(const float4*)(rp + nt * 4);
                acc[nt][0] += r4.x; acc[nt][1] += r4.y;
                acc[nt][2] += r4.z; acc[nt][3] += r4.w;
            }
            float hn[2][2];
#pragma unroll
            for (int rh = 0; rh < 2; ++rh)
#pragma unroll
                for (int ff = 0; ff < 2; ++ff) {
                    int q = rh * 2 + ff;
                    float cn = sigfast(acc[1][q]) * creg[q] + sigfast(acc[0][q]) * tanhfast(acc[2][q]);
                    hn[rh][ff] = sigfast(acc[3][q]) * tanhfast(cn);
                    creg[q] = cn;
                }

            // push h_{t+1} slice (fp16) into all peers' hs[b^1] + arrive slice barrier
            if (t < 511) {
                uint32_t bufoff = (uint32_t)(b ^ 1) * HBUFB;
#pragma unroll
                for (int rh = 0; rh < 2; ++rh) {
                    uint32_t hv = pack_h2(hn[rh][0], hn[rh][1]);
#pragma unroll
                    for (int p = 0; p < 8; ++p)
                        st_cluster_u32(peer_hs[p] + bufoff + hoff[rh], hv);
                }
#pragma unroll
                for (int p = 0; p < 8; ++p)
                    mbar_arrive_rel(peer_mb[p] + ((b ^ 1) * 8 + nf) * 8);
            }

            // fp32 h to output (off the critical path)
            float* dst = d_out + (size_t)t * BF + (size_t)mb * 4096;
#pragma unroll
            for (int rh = 0; rh < 2; ++rh)
                *(float2*)(dst + (gID + rh * 8) * 256 + nf * 32 + cg * 8 + 2 * tig) =
                    make_float2(hn[rh][0], hn[rh][1]);
        }
        // no bottom sync: next-iter slice waits provide all ordering
    }

    asm volatile("barrier.cluster.arrive.aligned;" ::: "memory");
    asm volatile("barrier.cluster.wait.aligned;" ::: "memory");
}

extern "C" void kernel_launch(void* const* d_in, const int* in_sizes, int n_in,
                              void* d_out, int out_size) {
    const float* x   = (const float*)d_in[0];
    const float* lf  = (const float*)d_in[1];
    const float* Wi  = (const float*)d_in[2];
    const float* bi  = (const float*)d_in[3];
    const float* Wih = (const float*)d_in[4];
    const float* Whh = (const float*)d_in[5];
    const float* bih = (const float*)d_in[6];
    const float* bhh = (const float*)d_in[7];
    float* out = (float*)d_out;

    cudaFuncSetAttribute(step0_kernel, cudaFuncAttributeMaxDynamicSharedMemorySize, 98304);

    prep_kernel<<<1152, 256>>>(Wih, Whh, bih, bhh, Wi);
    init_kernel<<<32, 256>>>(x, bi);
    step0_kernel<<<128, 256, 98304>>>(lf, out);
    lstm_kernel<<<128, 256>>>(out);
}

// round 14
// speedup vs baseline: 1.8016x; 1.5642x over previous
#include <cuda_runtime.h>
#include <cuda_fp16.h>
#include <cstdint>

#define B 256
#define L 128
#define F 256
#define S 512
#define BF (B*F)
#define G4F 1024

// ---- static device scratch (no allocation) ----
__device__ __half g_Wch[G4F * F];   // combined W_ih+W_hh, permuted [nf*128+c][k], fp16
__device__ float  g_WihT[G4F * F];  // [(nf*256+k)*128 + c]  (permuted c)
__device__ float  g_WhhT[G4F * F];
__device__ float  g_WiT[L * F];     // [k*256 + f]
__device__ float  g_bc[G4F];        // permuted combined bias
__device__ float  g_init[B * F];
__device__ float  g_c1[B * F];

__device__ __forceinline__ float sigf(float x) { return 1.0f / (1.0f + expf(-x)); }
__device__ __forceinline__ float tanhfast(float x) {
    float r; asm("tanh.approx.f32 %0, %1;" : "=f"(r) : "f"(x)); return r;
}
__device__ __forceinline__ float sigfast(float x) { return 0.5f * tanhfast(0.5f * x) + 0.5f; }

// ---- cluster / mbarrier helpers ----
__device__ __forceinline__ void mbar_init(uint32_t mbar, uint32_t cnt) {
    asm volatile("mbarrier.init.shared.b64 [%0], %1;" :: "r"(mbar), "r"(cnt) : "memory");
}
__device__ __forceinline__ void mbar_expect_tx(uint32_t mbar, uint32_t bytes) {
    asm volatile("mbarrier.arrive.expect_tx.shared.b64 _, [%0], %1;"
                 :: "r"(mbar), "r"(bytes) : "memory");
}
__device__ __forceinline__ void mbar_wait_cl(uint32_t mbar, uint32_t parity) {
    asm volatile(
        "{\n\t.reg .pred P;\n"
        "WL%=:\n\t"
        "mbarrier.try_wait.parity.acquire.cluster.shared::cta.b64 P, [%0], %1, 0x989680;\n\t"
        "@P bra WD%=;\n\t"
        "bra WL%=;\n"
        "WD%=:\n\t}"
        :: "r"(mbar), "r"(parity) : "memory");
}
__device__ __forceinline__ uint32_t mapa_u32(uint32_t local, uint32_t rank) {
    uint32_t r;
    asm("mapa.shared::cluster.u32 %0, %1, %2;" : "=r"(r) : "r"(local), "r"(rank));
    return r;
}
// remote store that also credits tx bytes on the co-located remote mbarrier
__device__ __forceinline__ void st_async_b32(uint32_t daddr, uint32_t v, uint32_t mbar) {
    asm volatile("st.async.shared::cluster.mbarrier::complete_tx::bytes.b32 [%0], %1, [%2];"
                 :: "r"(daddr), "r"(v), "r"(mbar) : "memory");
}
__device__ __forceinline__ uint32_t pack_h2(float a, float b) {
    __half2 h = __floats2half2_rn(a, b);
    return *(uint32_t*)&h;
}

// ---- P0: weight prep ----
// col permutation within a 128-col slice: c = (j>>3)*32 + gate*8 + (j&7)
__global__ void prep_kernel(const float* __restrict__ Wih, const float* __restrict__ Whh,
                            const float* __restrict__ bih, const float* __restrict__ bhh,
                            const float* __restrict__ Wi) {
    int bid = blockIdx.x, tid = threadIdx.x;
    if (bid < 1024) {
        int r = bid, k = tid;
        int g = r >> 8;
        int jj = r & 255;
        int nf = jj >> 5;
        int j  = jj & 31;
        int c  = ((j >> 3) << 5) + (g << 3) + (j & 7);
        float wih = Wih[r * 256 + k];
        float whh = Whh[r * 256 + k];
        g_Wch[(nf * 128 + c) * 256 + k] = __float2half_rn(wih + whh);
        g_WihT[(nf * 256 + k) * 128 + c] = wih;
        g_WhhT[(nf * 256 + k) * 128 + c] = whh;
        if (k == 0) g_bc[nf * 128 + c] = bih[r] + bhh[r];
    } else {
        int k = bid - 1024;
        int f = tid;
        g_WiT[k * 256 + f] = Wi[f * 128 + k];
    }
}

// ---- P1: init = elu(x @ Wi.T + bi) ----
__global__ void init_kernel(const float* __restrict__ x, const float* __restrict__ bi) {
    __shared__ float xs[32 * 128];
    int bid = blockIdx.x, tid = threadIdx.x;
    int bt = bid >> 2, ft = bid & 3;
    for (int i = tid; i < 32 * 128; i += 256)
        xs[i] = x[(bt * 32 + (i >> 7)) * 128 + (i & 127)];
    __syncthreads();
    int tx = tid & 15, ty = tid >> 4;
    int b0 = ty * 2;
    int f0 = ft * 64 + tx * 4;
    float acc[2][4] = {};
#pragma unroll 4
    for (int k = 0; k < 128; ++k) {
        float4 w = *(const float4*)&g_WiT[k * 256 + f0];
        float x0 = xs[b0 * 128 + k];
        float x1 = xs[(b0 + 1) * 128 + k];
        acc[0][0] += x0 * w.x; acc[0][1] += x0 * w.y; acc[0][2] += x0 * w.z; acc[0][3] += x0 * w.w;
        acc[1][0] += x1 * w.x; acc[1][1] += x1 * w.y; acc[1][2] += x1 * w.z; acc[1][3] += x1 * w.w;
    }
#pragma unroll
    for (int r = 0; r < 2; ++r)
#pragma unroll
        for (int cc = 0; cc < 4; ++cc) {
            float v = acc[r][cc] + bi[f0 + cc];
            v = (v > 0.0f) ? v : expm1f(v);
            g_init[(bt * 32 + b0 + r) * 256 + f0 + cc] = v;
        }
}

// ---- P2: step 0 (inp = last_feat, h = c = init) ----
__global__ void step0_kernel(const float* __restrict__ lf, float* __restrict__ d_out) {
    extern __shared__ float sm[];
    float* lfs = sm;
    float* ins = lfs + 16 * 256;
    float* wih = ins + 16 * 256;
    float* whh = wih + 64 * 128;
    int tid = threadIdx.x;
    int nf = blockIdx.x & 7, mbt = blockIdx.x >> 3;
    for (int i = tid; i < 16 * 256; i += 256) {
        int gi = (mbt * 16 + (i >> 8)) * 256 + (i & 255);
        lfs[i] = lf[gi];
        ins[i] = g_init[gi];
    }
    int tx = tid & 31, ty = tid >> 5;
    int c0 = tx * 4;
    float acc[2][4] = {};
    for (int kc = 0; kc < 4; ++kc) {
        __syncthreads();
        for (int i = tid; i < 64 * 128; i += 256) {
            int k = kc * 64 + (i >> 7), c = i & 127;
            wih[i] = g_WihT[(nf * 256 + k) * 128 + c];
            whh[i] = g_WhhT[(nf * 256 + k) * 128 + c];
        }
        __syncthreads();
#pragma unroll 4
        for (int k = 0; k < 64; ++k) {
            float4 a4 = *(const float4*)&wih[k * 128 + c0];
            float4 b4 = *(const float4*)&whh[k * 128 + c0];
#pragma unroll
            for (int e = 0; e < 2; ++e) {
                int b = ty + 8 * e;
                float lv = lfs[b * 256 + kc * 64 + k];
                float iv = ins[b * 256 + kc * 64 + k];
                acc[e][0] += lv * a4.x + iv * b4.x;
                acc[e][1] += lv * a4.y + iv * b4.y;
                acc[e][2] += lv * a4.z + iv * b4.z;
                acc[e][3] += lv * a4.w + iv * b4.w;
            }
        }
    }
    __syncthreads();
    float* gss = lfs;
#pragma unroll
    for (int e = 0; e < 2; ++e)
#pragma unroll
        for (int cc = 0; cc < 4; ++cc)
            gss[(ty + 8 * e) * 132 + c0 + cc] = acc[e][cc];
    __syncthreads();
#pragma unroll
    for (int e2 = 0; e2 < 2; ++e2) {
        int li = tid + 256 * e2;
        int b = li >> 5, j = li & 31;
        int cb = ((j >> 3) << 5) + (j & 7);
        float iv = gss[b * 132 + cb]      + g_bc[nf * 128 + cb];
        float fv = gss[b * 132 + cb + 8]  + g_bc[nf * 128 + cb + 8];
        float gv = gss[b * 132 + cb + 16] + g_bc[nf * 128 + cb + 16];
        float ov = gss[b * 132 + cb + 24] + g_bc[nf * 128 + cb + 24];
        float cp = ins[b * 256 + nf * 32 + j];
        float cn = sigf(fv) * cp + sigf(iv) * tanhf(gv);
        float hn = sigf(ov) * tanhf(cn);
        int gi = (mbt * 16 + b) * 256 + nf * 32 + j;
        g_c1[gi] = cn;
        d_out[gi] = hn;
    }
}

// ---- fp16 mma helper (m16n8k16, fp32 accum) ----
__device__ __forceinline__ void mma16(float* d, const unsigned* a, unsigned b0, unsigned b1) {
    asm volatile(
        "mma.sync.aligned.m16n8k16.row.col.f32.f16.f16.f32 "
        "{%0,%1,%2,%3}, {%4,%5,%6,%7}, {%8,%9}, {%0,%1,%2,%3};"
        : "+f"(d[0]), "+f"(d[1]), "+f"(d[2]), "+f"(d[3])
        : "r"(a[0]), "r"(a[1]), "r"(a[2]), "r"(a[3]), "r"(b0), "r"(b1));
}

#define HSTRIDE 264                 // halves per row (528 B) -> conflict-free fragments
#define HBUFB   (16 * HSTRIDE * 2)  // bytes per h buffer (8448)
#define SLICE_TX 1024               // bytes per slice push (16 rows x 32 feats x fp16)

// ---- P3: persistent recurrence, t = 1..511 ----
// 128 CTAs x 256 thr, clusters of 8 (= batch group mb). nf = bid&7.
// h lives ONLY in SMEM (fp16). Pushes are st.async with transaction accounting on
// per-slice mbarriers (count=1, driven by expect_tx) -- NO mbarrier.arrive traffic.
__global__ void __cluster_dims__(8, 1, 1) __launch_bounds__(256, 1)
lstm_kernel(float* __restrict__ d_out) {
    __shared__ __align__(16) __half hs[2][16 * HSTRIDE];
    __shared__ float red[128 * 20];
    __shared__ __align__(8) unsigned long long mbars[16];   // [buf][slice]

    int tid = threadIdx.x;
    int nf = blockIdx.x & 7, mb = blockIdx.x >> 3;
    int warp = tid >> 5, lane = tid & 31;
    int cg = warp & 3, ks = warp >> 2;
    int gID = lane >> 2, tig = lane & 3;

    uint32_t hsb = (uint32_t)__cvta_generic_to_shared(&hs[0][0]);
    uint32_t mbb = (uint32_t)__cvta_generic_to_shared(&mbars[0]);

    if (tid == 0) {
#pragma unroll
        for (int i = 0; i < 16; ++i) mbar_init(mbb + i * 8, 1);
        // arm both buffers: buf1 for t=1 (prologue), buf0 for t=2
#pragma unroll
        for (int i = 0; i < 16; ++i) mbar_expect_tx(mbb + i * 8, SLICE_TX);
    }

    // weight fragments (fp16): warp covers cols [cg*32,+32), k in [ks*128,+128)
    unsigned breg[4][8][2];
#pragma unroll
    for (int nt = 0; nt < 4; ++nt)
#pragma unroll
        for (int kb = 0; kb < 8; ++kb) {
            const __half* wp = &g_Wch[(nf * 128 + cg * 32 + nt * 8 + gID) * 256
                                      + ks * 128 + kb * 16 + 2 * tig];
            breg[nt][kb][0] = *(const uint32_t*)wp;
            breg[nt][kb][1] = *(const uint32_t*)(wp + 8);
        }

    float bias[4][2];
#pragma unroll
    for (int nt = 0; nt < 4; ++nt) {
        float b0 = g_bc[nf * 128 + cg * 32 + nt * 8 + 2 * tig];
        float b1 = g_bc[nf * 128 + cg * 32 + nt * 8 + 2 * tig + 1];
        bias[nt][0] = ks ? 0.0f : b0;
        bias[nt][1] = ks ? 0.0f : b1;
    }

    uint32_t peer_hs[8], peer_mb[8];
#pragma unroll
    for (int p = 0; p < 8; ++p) {
        peer_hs[p] = mapa_u32(hsb, p);
        peer_mb[p] = mapa_u32(mbb, p);
    }

    float creg[4];
    uint32_t hoff[2];
    if (ks == 0) {
#pragma unroll
        for (int rh = 0; rh < 2; ++rh) {
#pragma unroll
            for (int ff = 0; ff < 2; ++ff)
                creg[rh * 2 + ff] =
                    g_c1[(mb * 16 + gID + rh * 8) * 256 + nf * 32 + cg * 8 + 2 * tig + ff];
            hoff[rh] = (uint32_t)((gID + rh * 8) * HSTRIDE + nf * 32 + cg * 8 + 2 * tig) * 2;
        }
    }
    __syncthreads();
    // cluster-wide: all mbarriers armed before any st.async can credit them
    asm volatile("barrier.cluster.arrive.aligned;" ::: "memory");
    asm volatile("barrier.cluster.wait.aligned;" ::: "memory");

    // prologue: push own slice of h_1 (d_out row 0, from step0) into buffer 1 everywhere
    if (ks == 0) {
        const float* src = d_out + (size_t)mb * 4096;
#pragma unroll
        for (int rh = 0; rh < 2; ++rh) {
            float2 v = *(const float2*)(src + (gID + rh * 8) * 256 + nf * 32 + cg * 8 + 2 * tig);
            uint32_t hv = pack_h2(v.x, v.y);
#pragma unroll
            for (int p = 0; p < 8; ++p)
                st_async_b32(peer_hs[p] + HBUFB + hoff[rh], hv, peer_mb[p] + (8 + nf) * 8);
        }
    }

    unsigned ph[2] = {0u, 0u};

    for (int t = 1; t < 512; ++t) {
        int b = t & 1;
        const __half* hb = &hs[b][0];

        float acc[4][4];
#pragma unroll
        for (int nt = 0; nt < 4; ++nt) {
            acc[nt][0] = bias[nt][0]; acc[nt][1] = bias[nt][1];
            acc[nt][2] = bias[nt][0]; acc[nt][3] = bias[nt][1];
        }

        // mma slice-by-slice; wait each slice barrier just-in-time
#pragma unroll
        for (int sl = 0; sl < 4; ++sl) {
            int j = ks * 4 + sl;
            mbar_wait_cl(mbb + (b * 8 + j) * 8, ph[b]);
#pragma unroll
            for (int kb2 = 0; kb2 < 2; ++kb2) {
                int k0 = j * 32 + kb2 * 16;
                unsigned a[4];
                a[0] = *(const uint32_t*)&hb[gID * HSTRIDE + k0 + 2 * tig];
                a[1] = *(const uint32_t*)&hb[(gID + 8) * HSTRIDE + k0 + 2 * tig];
                a[2] = *(const uint32_t*)&hb[gID * HSTRIDE + k0 + 8 + 2 * tig];
                a[3] = *(const uint32_t*)&hb[(gID + 8) * HSTRIDE + k0 + 8 + 2 * tig];
                int kb = sl * 2 + kb2;
#pragma unroll
                for (int nt = 0; nt < 4; ++nt)
                    mma16(acc[nt], a, breg[nt][kb][0], breg[nt][kb][1]);
            }
        }
        ph[b] ^= 1u;

        if (ks == 1) {
            float* rp = &red[(cg * 32 + lane) * 20];
#pragma unroll
            for (int nt = 0; nt < 4; ++nt)
                *(float4*)(rp + nt * 4) = make_float4(acc[nt][0], acc[nt][1], acc[nt][2], acc[nt][3]);
        }
        __syncthreads();   // all warps observed buffer-b phase flip; red visible

        // re-arm buffer b for step t+2 (producers push at t+1 iff t+1 < 511)
        if (tid == 0 && t <= 509) {
#pragma unroll
            for (int j = 0; j < 8; ++j)
                mbar_expect_tx(mbb + (b * 8 + j) * 8, SLICE_TX);
        }

        if (ks == 0) {
            const float* rp = &red[(cg * 32 + lane) * 20];
#pragma unroll
            for (int nt = 0; nt < 4; ++nt) {
                float4 r4 = *(const float4*)(rp + nt * 4);
                acc[nt][0] += r4.x; acc[nt][1] += r4.y;
                acc[nt][2] += r4.z; acc[nt][3] += r4.w;
            }
            float hn[2][2];
#pragma unroll
            for (int rh = 0; rh < 2; ++rh)
#pragma unroll
                for (int ff = 0; ff < 2; ++ff) {
                    int q = rh * 2 + ff;
                    float cn = sigfast(acc[1][q]) * creg[q] + sigfast(acc[0][q]) * tanhfast(acc[2][q]);
                    hn[rh][ff] = sigfast(acc[3][q]) * tanhfast(cn);
                    creg[q] = cn;
                }

            // push h_{t+1} slice into all peers' hs[b^1] via st.async (tx-credited)
            if (t < 511) {
                uint32_t bufoff = (uint32_t)(b ^ 1) * HBUFB;
                uint32_t mslice = ((b ^ 1) * 8 + nf) * 8;
#pragma unroll
                for (int rh = 0; rh < 2; ++rh) {
                    uint32_t hv = pack_h2(hn[rh][0], hn[rh][1]);
#pragma unroll
                    for (int p = 0; p < 8; ++p)
                        st_async_b32(peer_hs[p] + bufoff + hoff[rh], hv, peer_mb[p] + mslice);
                }
            }

            // fp32 h to output (off the critical path)
            float* dst = d_out + (size_t)t * BF + (size_t)mb * 4096;
#pragma unroll
            for (int rh = 0; rh < 2; ++rh)
                *(float2*)(dst + (gID + rh * 8) * 256 + nf * 32 + cg * 8 + 2 * tig) =
                    make_float2(hn[rh][0], hn[rh][1]);
        }
        // no bottom sync: next-iter slice waits provide all ordering
    }

    asm volatile("barrier.cluster.arrive.aligned;" ::: "memory");
    asm volatile("barrier.cluster.wait.aligned;" ::: "memory");
}

extern "C" void kernel_launch(void* const* d_in, const int* in_sizes, int n_in,
                              void* d_out, int out_size) {
    const float* x   = (const float*)d_in[0];
    const float* lf  = (const float*)d_in[1];
    const float* Wi  = (const float*)d_in[2];
    const float* bi  = (const float*)d_in[3];
    const float* Wih = (const float*)d_in[4];
    const float* Whh = (const float*)d_in[5];
    const float* bih = (const float*)d_in[6];
    const float* bhh = (const float*)d_in[7];
    float* out = (float*)d_out;

    cudaFuncSetAttribute(step0_kernel, cudaFuncAttributeMaxDynamicSharedMemorySize, 98304);

    prep_kernel<<<1152, 256>>>(Wih, Whh, bih, bhh, Wi);
    init_kernel<<<32, 256>>>(x, bi);
    step0_kernel<<<128, 256, 98304>>>(lf, out);
    lstm_kernel<<<128, 256>>>(out);
}